// round 1
// baseline (speedup 1.0000x reference)
#include <cuda_runtime.h>
#include <math.h>

#define PP  20000
#define MMR 20000
#define NN  16
#define DD  128
#define HH  8
#define DFF 512

// ---------------- scratch (static device memory; no allocations) ----------------
__device__ float g_q  [(size_t)PP * DD * 3];
__device__ float g_k  [(size_t)MMR * DD * 3];
__device__ float g_v  [(size_t)MMR * DD * 3];
__device__ float g_t2 [(size_t)PP * DD * 3];
__device__ float g_t2o[(size_t)PP * DD * 3];
__device__ float g_y  [(size_t)PP * DD * 3];
__device__ float g_h1 [(size_t)PP * DFF * 3];
__device__ float g_ff [(size_t)PP * DD * 3];

// ---------------------------------------------------------------------------
// Generic VN linear: Y[r, o, i] = sum_c X[r, c, i] * W[c, o]
// X row-major (rows, K*3), W row-major (K, Cout), Y row-major (rows, Cout*3)
// grid: (Cout/64, rows/32, 3), block 256. Tile 32 rows x 64 outs, thread 2x4.
// ---------------------------------------------------------------------------
template <int K>
__global__ void vn_gemm_kernel(const float* __restrict__ X,
                               const float* __restrict__ W,
                               float* __restrict__ Y, int Cout)
{
    const int i  = blockIdx.z;
    const int r0 = blockIdx.y * 32;
    const int o0 = blockIdx.x * 64;
    const int t  = threadIdx.x;
    const int to = t & 15;   // 16 groups of 4 outs
    const int tr = t >> 4;   // 16 groups of 2 rows

    __shared__ float Xs[32][33];   // [c][r] (+1 pad)
    __shared__ float Ws[32][64];   // [c][o]

    float acc[2][4] = {{0.f,0.f,0.f,0.f},{0.f,0.f,0.f,0.f}};
    const int ldx = K * 3;

    #pragma unroll 1
    for (int c0 = 0; c0 < K; c0 += 32) {
        // X tile: 32c x 32r (c fastest across threads for contiguous-ish reads)
        #pragma unroll
        for (int j = 0; j < 4; j++) {
            int e = t + 256 * j;          // 1024 elements
            int c = e & 31;
            int r = e >> 5;
            Xs[c][r] = X[(size_t)(r0 + r) * ldx + (c0 + c) * 3 + i];
        }
        // W tile: 32c x 64o (coalesced)
        #pragma unroll
        for (int j = 0; j < 8; j++) {
            int e = t + 256 * j;          // 2048 elements
            int c = e >> 6;
            int o = e & 63;
            Ws[c][o] = W[(size_t)(c0 + c) * Cout + o0 + o];
        }
        __syncthreads();
        #pragma unroll
        for (int c = 0; c < 32; c++) {
            float a0 = Xs[c][2 * tr];
            float a1 = Xs[c][2 * tr + 1];
            float4 w = *reinterpret_cast<const float4*>(&Ws[c][to * 4]);
            acc[0][0] += a0 * w.x; acc[0][1] += a0 * w.y;
            acc[0][2] += a0 * w.z; acc[0][3] += a0 * w.w;
            acc[1][0] += a1 * w.x; acc[1][1] += a1 * w.y;
            acc[1][2] += a1 * w.z; acc[1][3] += a1 * w.w;
        }
        __syncthreads();
    }

    #pragma unroll
    for (int rr = 0; rr < 2; rr++) {
        size_t rowb = (size_t)(r0 + 2 * tr + rr) * (Cout * 3);
        #pragma unroll
        for (int oo = 0; oo < 4; oo++) {
            Y[rowb + (o0 + to * 4 + oo) * 3 + i] = acc[rr][oo];
        }
    }
}

// ---------------------------------------------------------------------------
// Attention: one CTA (128 threads) per point p. Thread = channel d.
// ---------------------------------------------------------------------------
__global__ void attn_kernel(const float* __restrict__ sh,
                            const float* __restrict__ dist,
                            const float* __restrict__ gw1,
                            const float* __restrict__ gb1,
                            const float* __restrict__ gw2,
                            const float* __restrict__ gb2,
                            const int* __restrict__ idxp)
{
    const int p = blockIdx.x;
    const int d = threadIdx.x;              // 0..127
    const int h = d >> 4;                   // head for this channel

    __shared__ float v_s[NN][DD][3];        // 24 KB
    __shared__ float pos_s[NN][DD];         // 8 KB
    __shared__ float sh_s[NN][3];
    __shared__ float att_s[NN][HH];
    __shared__ float rh_s[NN][HH];
    __shared__ int   idx_s[NN];
    __shared__ float w1_s[DD][HH];          // 4 KB

    // q for this channel
    const float* qp = g_q + (size_t)p * (DD * 3) + d * 3;
    float q0 = qp[0], q1 = qp[1], q2 = qp[2];

    if (d < NN) idx_s[d] = idxp[(size_t)p * NN + d];
    if (d < NN * 3) ((float*)sh_s)[d] = sh[(size_t)p * ((NN + 1) * 3) + 3 + d];
    #pragma unroll
    for (int e = d; e < DD * HH; e += 128) ((float*)w1_s)[e] = gw1[e];
    __syncthreads();

    #pragma unroll 4
    for (int n = 0; n < NN; n++) {
        size_t base = (size_t)idx_s[n] * (DD * 3) + d * 3;
        float k0 = g_k[base + 0], k1 = g_k[base + 1], k2 = g_k[base + 2];
        v_s[n][d][0] = g_v[base + 0];
        v_s[n][d][1] = g_v[base + 1];
        v_s[n][d][2] = g_v[base + 2];
        float dot = q0 * k0 + q1 * k1 + q2 * k2;
        dot += __shfl_xor_sync(0xffffffffu, dot, 8);
        dot += __shfl_xor_sync(0xffffffffu, dot, 4);
        dot += __shfl_xor_sync(0xffffffffu, dot, 2);
        dot += __shfl_xor_sync(0xffffffffu, dot, 1);
        if ((d & 15) == 0) att_s[n][h] = dot;
        pos_s[n][d] = (k0 - q0) * sh_s[n][0] + (k1 - q1) * sh_s[n][1]
                    + (k2 - q2) * sh_s[n][2];
    }
    __syncthreads();

    // pos MLP layer 1: thread = (n, j), 16*8 = 128
    {
        int n = d >> 3, j = d & 7;
        float acc = gb1[j];
        #pragma unroll 8
        for (int c = 0; c < DD; c++) acc += pos_s[n][c] * w1_s[c][j];
        rh_s[n][j] = fmaxf(acc, 0.0f);
    }
    __syncthreads();

    // layer 2 + combine with dot attention and distance bias
    {
        int n = d >> 3, hh = d & 7;
        float acc = gb2[hh];
        #pragma unroll
        for (int j = 0; j < HH; j++) acc += rh_s[n][j] * gw2[j * HH + hh];
        float da = dist[(size_t)p * (NN * HH) + n * HH + hh];
        att_s[n][hh] = (att_s[n][hh] + acc + da) * 0.25f;  // 1/sqrt(DPH)
    }
    __syncthreads();

    // softmax over n per head
    if (d < HH) {
        float m = -1e30f;
        #pragma unroll
        for (int n = 0; n < NN; n++) m = fmaxf(m, att_s[n][d]);
        float s = 0.f;
        #pragma unroll
        for (int n = 0; n < NN; n++) { float e = expf(att_s[n][d] - m); att_s[n][d] = e; s += e; }
        float inv = 1.f / s;
        #pragma unroll
        for (int n = 0; n < NN; n++) att_s[n][d] *= inv;
    }
    __syncthreads();

    float o0 = 0.f, o1 = 0.f, o2 = 0.f;
    #pragma unroll
    for (int n = 0; n < NN; n++) {
        float a = att_s[n][h];
        o0 += a * v_s[n][d][0];
        o1 += a * v_s[n][d][1];
        o2 += a * v_s[n][d][2];
    }
    float* op = g_t2 + (size_t)p * (DD * 3) + d * 3;
    op[0] = o0; op[1] = o1; op[2] = o2;
}

// ---------------------------------------------------------------------------
// Fused residual + vn_layernorm: O = vn_ln(A + B)
// grid: P blocks, 128 threads (thread = channel d)
// ---------------------------------------------------------------------------
__global__ void vn_ln_kernel(const float* __restrict__ A,
                             const float* __restrict__ B,
                             const float* __restrict__ gam,
                             const float* __restrict__ bet,
                             float* __restrict__ O)
{
    const int p = blockIdx.x;
    const int d = threadIdx.x;
    size_t base = (size_t)p * (DD * 3) + d * 3;
    float z0 = A[base + 0] + B[base + 0];
    float z1 = A[base + 1] + B[base + 1];
    float z2 = A[base + 2] + B[base + 2];
    float n = sqrtf(z0 * z0 + z1 * z1 + z2 * z2);

    float s1 = n, s2 = n * n;
    #pragma unroll
    for (int off = 16; off; off >>= 1) {
        s1 += __shfl_xor_sync(0xffffffffu, s1, off);
        s2 += __shfl_xor_sync(0xffffffffu, s2, off);
    }
    __shared__ float sm1[4], sm2[4];
    int w = d >> 5;
    if ((d & 31) == 0) { sm1[w] = s1; sm2[w] = s2; }
    __syncthreads();
    float S1 = sm1[0] + sm1[1] + sm1[2] + sm1[3];
    float S2 = sm2[0] + sm2[1] + sm2[2] + sm2[3];
    float mu  = S1 * (1.0f / DD);
    float var = S2 * (1.0f / DD) - mu * mu;
    float nh  = (n - mu) * rsqrtf(var + 1e-5f) * gam[d] + bet[d];
    float sc  = nh / (n + 1e-6f);
    O[base + 0] = z0 * sc;
    O[base + 1] = z1 * sc;
    O[base + 2] = z2 * sc;
}

// ---------------------------------------------------------------------------
// FF1: h1 = vn_relu(Y @ W1, Y @ D1). All 3 components per thread (vn_relu
// couples them). grid: (DFF/32, P/32), block 256. Thread = (r, 4 f's).
// ---------------------------------------------------------------------------
__global__ void vn_ff1_kernel(const float* __restrict__ Yin,
                              const float* __restrict__ W1,
                              const float* __restrict__ D1,
                              float* __restrict__ H1)
{
    const int r0 = blockIdx.y * 32;
    const int f0 = blockIdx.x * 32;
    const int t  = threadIdx.x;
    const int r  = t & 31;
    const int fg = t >> 5;   // 0..7, handles f = fg*4 .. fg*4+3

    __shared__ float Xs[32][3][33];   // [c][i][r]
    __shared__ float W1s[32][32];     // [c][f]
    __shared__ float D1s[32][32];

    float a[4][3] = {};
    float b[4][3] = {};

    #pragma unroll 1
    for (int c0 = 0; c0 < DD; c0 += 32) {
        // X tile: rows r0..r0+31, 96 contiguous floats per row
        #pragma unroll
        for (int j = 0; j < 12; j++) {
            int e = t + 256 * j;        // 3072 elements
            int rr  = e / 96;
            int off = e - rr * 96;
            int c   = off / 3;
            int ii  = off - c * 3;
            Xs[c][ii][rr] = Yin[(size_t)(r0 + rr) * (DD * 3) + c0 * 3 + off];
        }
        #pragma unroll
        for (int j = 0; j < 4; j++) {
            int e = t + 256 * j;        // 1024
            int c = e >> 5;
            int f = e & 31;
            W1s[c][f] = W1[(size_t)(c0 + c) * DFF + f0 + f];
            D1s[c][f] = D1[(size_t)(c0 + c) * DFF + f0 + f];
        }
        __syncthreads();
        #pragma unroll
        for (int c = 0; c < 32; c++) {
            float x0 = Xs[c][0][r], x1 = Xs[c][1][r], x2 = Xs[c][2][r];
            float4 w = *reinterpret_cast<const float4*>(&W1s[c][fg * 4]);
            float4 dd = *reinterpret_cast<const float4*>(&D1s[c][fg * 4]);
            a[0][0] += x0 * w.x;  a[0][1] += x1 * w.x;  a[0][2] += x2 * w.x;
            a[1][0] += x0 * w.y;  a[1][1] += x1 * w.y;  a[1][2] += x2 * w.y;
            a[2][0] += x0 * w.z;  a[2][1] += x1 * w.z;  a[2][2] += x2 * w.z;
            a[3][0] += x0 * w.w;  a[3][1] += x1 * w.w;  a[3][2] += x2 * w.w;
            b[0][0] += x0 * dd.x; b[0][1] += x1 * dd.x; b[0][2] += x2 * dd.x;
            b[1][0] += x0 * dd.y; b[1][1] += x1 * dd.y; b[1][2] += x2 * dd.y;
            b[2][0] += x0 * dd.z; b[2][1] += x1 * dd.z; b[2][2] += x2 * dd.z;
            b[3][0] += x0 * dd.w; b[3][1] += x1 * dd.w; b[3][2] += x2 * dd.w;
        }
        __syncthreads();
    }

    float* hp = H1 + (size_t)(r0 + r) * (DFF * 3) + (size_t)(f0 + fg * 4) * 3;
    #pragma unroll
    for (int ff = 0; ff < 4; ff++) {
        float dot = a[ff][0] * b[ff][0] + a[ff][1] * b[ff][1] + a[ff][2] * b[ff][2];
        float ksq = b[ff][0] * b[ff][0] + b[ff][1] * b[ff][1] + b[ff][2] * b[ff][2];
        float s = (dot >= 0.0f) ? 0.0f : (dot / (ksq + 1e-6f));
        hp[ff * 3 + 0] = a[ff][0] - s * b[ff][0];
        hp[ff * 3 + 1] = a[ff][1] - s * b[ff][1];
        hp[ff * 3 + 2] = a[ff][2] - s * b[ff][2];
    }
}

// ---------------------------------------------------------------------------
extern "C" void kernel_launch(void* const* d_in, const int* in_sizes, int n_in,
                              void* d_out, int out_size)
{
    const float* tgt   = (const float*)d_in[0];
    const float* mem   = (const float*)d_in[1];
    const float* sh    = (const float*)d_in[2];
    const float* dist  = (const float*)d_in[3];
    const float* Wq    = (const float*)d_in[4];
    const float* Wk    = (const float*)d_in[5];
    const float* Wv    = (const float*)d_in[6];
    const float* Wo    = (const float*)d_in[7];
    const float* gw1   = (const float*)d_in[8];
    const float* gb1   = (const float*)d_in[9];
    const float* gw2   = (const float*)d_in[10];
    const float* gb2   = (const float*)d_in[11];
    const float* ln1g  = (const float*)d_in[12];
    const float* ln1b  = (const float*)d_in[13];
    const float* ln2g  = (const float*)d_in[14];
    const float* ln2b  = (const float*)d_in[15];
    const float* ffw1  = (const float*)d_in[16];
    const float* ffd1  = (const float*)d_in[17];
    const float* ffw2  = (const float*)d_in[18];
    const int*   idxp  = (const int*)d_in[19];
    float* out = (float*)d_out;

    float *q, *k, *v, *t2, *t2o, *y, *h1, *ff;
    cudaGetSymbolAddress((void**)&q,   g_q);
    cudaGetSymbolAddress((void**)&k,   g_k);
    cudaGetSymbolAddress((void**)&v,   g_v);
    cudaGetSymbolAddress((void**)&t2,  g_t2);
    cudaGetSymbolAddress((void**)&t2o, g_t2o);
    cudaGetSymbolAddress((void**)&y,   g_y);
    cudaGetSymbolAddress((void**)&h1,  g_h1);
    cudaGetSymbolAddress((void**)&ff,  g_ff);

    dim3 gl(2, PP / 32, 3);   // Cout=128 linears

    vn_gemm_kernel<DD><<<gl, 256>>>(tgt, Wq, q, DD);
    vn_gemm_kernel<DD><<<gl, 256>>>(mem, Wk, k, DD);
    vn_gemm_kernel<DD><<<gl, 256>>>(mem, Wv, v, DD);

    attn_kernel<<<PP, 128>>>(sh, dist, gw1, gb1, gw2, gb2, idxp);

    vn_gemm_kernel<DD><<<gl, 256>>>(t2, Wo, t2o, DD);
    vn_ln_kernel<<<PP, 128>>>(tgt, t2o, ln1g, ln1b, y);

    vn_ff1_kernel<<<dim3(DFF / 32, PP / 32), 256>>>(y, ffw1, ffd1, h1);
    vn_gemm_kernel<DFF><<<gl, 256>>>(h1, ffw2, ff, DD);
    vn_ln_kernel<<<PP, 128>>>(y, ff, ln2g, ln2b, out);
}

// round 2
// speedup vs baseline: 1.5778x; 1.5778x over previous
#include <cuda_runtime.h>
#include <math.h>

#define PP  20000
#define MMR 20000
#define NN  16
#define DD  128
#define HH  8
#define DFF 512

// ---------------- scratch (static device memory; no allocations) ----------------
__device__ float g_q  [(size_t)PP * DD * 3];
__device__ float g_k  [(size_t)MMR * DD * 3];
__device__ float g_v  [(size_t)MMR * DD * 3];
__device__ float g_t2 [(size_t)PP * DD * 3];
__device__ float g_t2o[(size_t)PP * DD * 3];
__device__ float g_y  [(size_t)PP * DD * 3];
__device__ float g_h1 [(size_t)PP * DFF * 3];
__device__ float g_ff [(size_t)PP * DD * 3];

// Packed fp32x2 FMA (Blackwell): d = a*b + d per 32-bit lane, rn rounding.
__device__ __forceinline__ void fma2(float2& d, const float2 a, const float2 b)
{
    asm("fma.rn.f32x2 %0, %1, %2, %0;"
        : "+l"(*reinterpret_cast<unsigned long long*>(&d))
        : "l"(*reinterpret_cast<const unsigned long long*>(&a)),
          "l"(*reinterpret_cast<const unsigned long long*>(&b)));
}

// ---------------------------------------------------------------------------
// VN GEMM, Cout = 128: Y[p, o, i] = sum_c X[p, c, i] * W[c, o]
// Flattened rows rho = 3*p + i. CTA tile: 96 flat rows (32 points) x 128 outs.
// 128 threads; thread tile 12 rows x 8 cols, rows packed pairwise in f32x2.
// W stored in smem duplicated ({w,w,w',w'} per 16B) so LDS.128 feeds FFMA2
// directly; column mapping o = 2*(tx+16j)+b keeps LDS phases conflict-free.
// ---------------------------------------------------------------------------
template <int K>
__global__ void __launch_bounds__(128, 3)
vn_gemm2(const float* __restrict__ X, const float* __restrict__ W,
         float* __restrict__ Y)
{
    const int tid = threadIdx.x;
    const int tx  = tid & 15;     // 16 col groups
    const int ty  = tid >> 4;     // 8 row groups (12 flat rows each)
    const int pb  = blockIdx.x * 32;   // base point

    __shared__ float  Xs[16 * 98];     // [k][flat row], stride 98 (pad)
    __shared__ float4 Wd[16 * 64];     // [k][16B unit], dup pairs

    float2 acc[6][8] = {};

    #pragma unroll 1
    for (int c0 = 0; c0 < K; c0 += 16) {
        __syncthreads();
        // X tile: 32 points x 48 floats (16 c * 3 i), fully coalesced
        #pragma unroll
        for (int jj = 0; jj < 12; jj++) {
            int e   = tid + 128 * jj;          // 1536 elems
            int pt  = e / 48;
            int off = e - pt * 48;
            float v = X[(size_t)(pb + pt) * (K * 3) + c0 * 3 + off];
            Xs[(off / 3) * 98 + pt * 3 + (off % 3)] = v;
        }
        // W tile, duplicated: 16 k x 128 o
        #pragma unroll
        for (int jj = 0; jj < 16; jj++) {
            int e = tid + 128 * jj;            // 2048 values
            int k = e >> 7;
            int o = e & 127;
            float w = W[(size_t)(c0 + k) * 128 + o];
            reinterpret_cast<float2*>(Wd)[k * 128 + o] = make_float2(w, w);
        }
        __syncthreads();
        #pragma unroll 4
        for (int k = 0; k < 16; k++) {
            float2 A[6];
            #pragma unroll
            for (int m = 0; m < 6; m++)
                A[m] = *reinterpret_cast<const float2*>(&Xs[k * 98 + ty * 12 + 2 * m]);
            #pragma unroll
            for (int j = 0; j < 4; j++) {
                float4 w4 = Wd[k * 64 + tx + 16 * j];
                float2 W0 = make_float2(w4.x, w4.y);
                float2 W1 = make_float2(w4.z, w4.w);
                #pragma unroll
                for (int m = 0; m < 6; m++) {
                    fma2(acc[m][2 * j],     A[m], W0);
                    fma2(acc[m][2 * j + 1], A[m], W1);
                }
            }
        }
    }

    #pragma unroll
    for (int r = 0; r < 12; r++) {
        int pt = pb + 4 * ty + r / 3;
        int i  = r % 3;
        #pragma unroll
        for (int co = 0; co < 8; co++) {
            int o = 2 * (tx + 16 * (co >> 1)) + (co & 1);
            float v = (r & 1) ? acc[r >> 1][co].y : acc[r >> 1][co].x;
            Y[(size_t)pt * 384 + o * 3 + i] = v;
        }
    }
}

// ---------------------------------------------------------------------------
// FF1: h1 = vn_relu(Y @ W1, Y @ D1). CTA tile: 32 points x 64 f-outs.
// 128 threads; thread: 12 flat rows (4 points) x 4 cols x 2 matrices.
// ---------------------------------------------------------------------------
__global__ void __launch_bounds__(128, 3)
vn_ff1_kernel(const float* __restrict__ Yin, const float* __restrict__ W1,
              const float* __restrict__ D1, float* __restrict__ H1)
{
    const int tid = threadIdx.x;
    const int tx  = tid & 15;
    const int ty  = tid >> 4;
    const int pb  = blockIdx.y * 32;
    const int f0  = blockIdx.x * 64;

    __shared__ float  Xs[16 * 98];
    __shared__ float4 Wd[2][16 * 32];

    float2 accA[6][4] = {};
    float2 accB[6][4] = {};

    #pragma unroll 1
    for (int c0 = 0; c0 < DD; c0 += 16) {
        __syncthreads();
        #pragma unroll
        for (int jj = 0; jj < 12; jj++) {
            int e   = tid + 128 * jj;
            int pt  = e / 48;
            int off = e - pt * 48;
            float v = Yin[(size_t)(pb + pt) * (DD * 3) + c0 * 3 + off];
            Xs[(off / 3) * 98 + pt * 3 + (off % 3)] = v;
        }
        #pragma unroll
        for (int jj = 0; jj < 8; jj++) {
            int e = tid + 128 * jj;            // 1024 per matrix
            int k = e >> 6;
            int o = e & 63;
            float wa = W1[(size_t)(c0 + k) * DFF + f0 + o];
            float wb = D1[(size_t)(c0 + k) * DFF + f0 + o];
            reinterpret_cast<float2*>(Wd[0])[k * 64 + o] = make_float2(wa, wa);
            reinterpret_cast<float2*>(Wd[1])[k * 64 + o] = make_float2(wb, wb);
        }
        __syncthreads();
        #pragma unroll 4
        for (int k = 0; k < 16; k++) {
            float2 A[6];
            #pragma unroll
            for (int m = 0; m < 6; m++)
                A[m] = *reinterpret_cast<const float2*>(&Xs[k * 98 + ty * 12 + 2 * m]);
            #pragma unroll
            for (int j = 0; j < 2; j++) {
                float4 wa4 = Wd[0][k * 32 + tx + 16 * j];
                float4 wb4 = Wd[1][k * 32 + tx + 16 * j];
                float2 Wa0 = make_float2(wa4.x, wa4.y);
                float2 Wa1 = make_float2(wa4.z, wa4.w);
                float2 Wb0 = make_float2(wb4.x, wb4.y);
                float2 Wb1 = make_float2(wb4.z, wb4.w);
                #pragma unroll
                for (int m = 0; m < 6; m++) {
                    fma2(accA[m][2 * j],     A[m], Wa0);
                    fma2(accA[m][2 * j + 1], A[m], Wa1);
                    fma2(accB[m][2 * j],     A[m], Wb0);
                    fma2(accB[m][2 * j + 1], A[m], Wb1);
                }
            }
        }
    }

    #pragma unroll
    for (int ptl = 0; ptl < 4; ptl++) {
        int p = pb + 4 * ty + ptl;
        #pragma unroll
        for (int co = 0; co < 4; co++) {
            int o = f0 + 2 * (tx + 16 * (co >> 1)) + (co & 1);
            float a[3], b[3];
            #pragma unroll
            for (int i = 0; i < 3; i++) {
                int r = 3 * ptl + i;
                a[i] = (r & 1) ? accA[r >> 1][co].y : accA[r >> 1][co].x;
                b[i] = (r & 1) ? accB[r >> 1][co].y : accB[r >> 1][co].x;
            }
            float dot = a[0] * b[0] + a[1] * b[1] + a[2] * b[2];
            float ksq = b[0] * b[0] + b[1] * b[1] + b[2] * b[2];
            float s = (dot >= 0.0f) ? 0.0f : (dot / (ksq + 1e-6f));
            float* hp = H1 + (size_t)p * (DFF * 3) + (size_t)o * 3;
            hp[0] = a[0] - s * b[0];
            hp[1] = a[1] - s * b[1];
            hp[2] = a[2] - s * b[2];
        }
    }
}

// ---------------------------------------------------------------------------
// Attention: one CTA (128 threads) per point p. Thread = channel d.
// v gathered directly from L2 in the weighted-sum loop (no 24KB smem tile).
// ---------------------------------------------------------------------------
__global__ void attn_kernel(const float* __restrict__ sh,
                            const float* __restrict__ dist,
                            const float* __restrict__ gw1,
                            const float* __restrict__ gb1,
                            const float* __restrict__ gw2,
                            const float* __restrict__ gb2,
                            const int* __restrict__ idxp)
{
    const int p = blockIdx.x;
    const int d = threadIdx.x;              // 0..127
    const int h = d >> 4;

    __shared__ float pos_s[NN][DD];         // 8 KB
    __shared__ float sh_s[NN][3];
    __shared__ float att_s[NN][HH];
    __shared__ float rh_s[NN][HH];
    __shared__ int   idx_s[NN];
    __shared__ float w1_s[DD][HH];          // 4 KB

    const float* qp = g_q + (size_t)p * (DD * 3) + d * 3;
    float q0 = qp[0], q1 = qp[1], q2 = qp[2];

    if (d < NN) idx_s[d] = idxp[(size_t)p * NN + d];
    if (d < NN * 3) ((float*)sh_s)[d] = sh[(size_t)p * ((NN + 1) * 3) + 3 + d];
    #pragma unroll
    for (int e = d; e < DD * HH; e += 128) ((float*)w1_s)[e] = gw1[e];
    __syncthreads();

    #pragma unroll 4
    for (int n = 0; n < NN; n++) {
        size_t base = (size_t)idx_s[n] * (DD * 3) + d * 3;
        float k0 = g_k[base + 0], k1 = g_k[base + 1], k2 = g_k[base + 2];
        float dot = q0 * k0 + q1 * k1 + q2 * k2;
        dot += __shfl_xor_sync(0xffffffffu, dot, 8);
        dot += __shfl_xor_sync(0xffffffffu, dot, 4);
        dot += __shfl_xor_sync(0xffffffffu, dot, 2);
        dot += __shfl_xor_sync(0xffffffffu, dot, 1);
        if ((d & 15) == 0) att_s[n][h] = dot;
        pos_s[n][d] = (k0 - q0) * sh_s[n][0] + (k1 - q1) * sh_s[n][1]
                    + (k2 - q2) * sh_s[n][2];
    }
    __syncthreads();

    // pos MLP layer 1: thread = (n, j)
    {
        int n = d >> 3, j = d & 7;
        float acc = gb1[j];
        const float4* pv = reinterpret_cast<const float4*>(&pos_s[n][0]);
        #pragma unroll 8
        for (int c4 = 0; c4 < DD / 4; c4++) {
            float4 pp = pv[c4];
            acc += pp.x * w1_s[c4 * 4 + 0][j] + pp.y * w1_s[c4 * 4 + 1][j]
                 + pp.z * w1_s[c4 * 4 + 2][j] + pp.w * w1_s[c4 * 4 + 3][j];
        }
        rh_s[n][j] = fmaxf(acc, 0.0f);
    }
    __syncthreads();

    {
        int n = d >> 3, hh = d & 7;
        float acc = gb2[hh];
        #pragma unroll
        for (int j = 0; j < HH; j++) acc += rh_s[n][j] * gw2[j * HH + hh];
        float da = dist[(size_t)p * (NN * HH) + n * HH + hh];
        att_s[n][hh] = (att_s[n][hh] + acc + da) * 0.25f;
    }
    __syncthreads();

    if (d < HH) {
        float m = -1e30f;
        #pragma unroll
        for (int n = 0; n < NN; n++) m = fmaxf(m, att_s[n][d]);
        float s = 0.f;
        #pragma unroll
        for (int n = 0; n < NN; n++) { float e = expf(att_s[n][d] - m); att_s[n][d] = e; s += e; }
        float inv = 1.f / s;
        #pragma unroll
        for (int n = 0; n < NN; n++) att_s[n][d] *= inv;
    }
    __syncthreads();

    float o0 = 0.f, o1 = 0.f, o2 = 0.f;
    #pragma unroll 4
    for (int n = 0; n < NN; n++) {
        float a = att_s[n][h];
        const float* vp = g_v + (size_t)idx_s[n] * (DD * 3) + d * 3;
        o0 += a * vp[0];
        o1 += a * vp[1];
        o2 += a * vp[2];
    }
    float* op = g_t2 + (size_t)p * (DD * 3) + d * 3;
    op[0] = o0; op[1] = o1; op[2] = o2;
}

// ---------------------------------------------------------------------------
// Fused residual + vn_layernorm: O = vn_ln(A + B). grid P, block 128.
// ---------------------------------------------------------------------------
__global__ void vn_ln_kernel(const float* __restrict__ A,
                             const float* __restrict__ B,
                             const float* __restrict__ gam,
                             const float* __restrict__ bet,
                             float* __restrict__ O)
{
    const int p = blockIdx.x;
    const int d = threadIdx.x;
    size_t base = (size_t)p * (DD * 3) + d * 3;
    float z0 = A[base + 0] + B[base + 0];
    float z1 = A[base + 1] + B[base + 1];
    float z2 = A[base + 2] + B[base + 2];
    float n = sqrtf(z0 * z0 + z1 * z1 + z2 * z2);

    float s1 = n, s2 = n * n;
    #pragma unroll
    for (int off = 16; off; off >>= 1) {
        s1 += __shfl_xor_sync(0xffffffffu, s1, off);
        s2 += __shfl_xor_sync(0xffffffffu, s2, off);
    }
    __shared__ float sm1[4], sm2[4];
    int w = d >> 5;
    if ((d & 31) == 0) { sm1[w] = s1; sm2[w] = s2; }
    __syncthreads();
    float S1 = sm1[0] + sm1[1] + sm1[2] + sm1[3];
    float S2 = sm2[0] + sm2[1] + sm2[2] + sm2[3];
    float mu  = S1 * (1.0f / DD);
    float var = S2 * (1.0f / DD) - mu * mu;
    float nh  = (n - mu) * rsqrtf(var + 1e-5f) * gam[d] + bet[d];
    float sc  = nh / (n + 1e-6f);
    O[base + 0] = z0 * sc;
    O[base + 1] = z1 * sc;
    O[base + 2] = z2 * sc;
}

// ---------------------------------------------------------------------------
extern "C" void kernel_launch(void* const* d_in, const int* in_sizes, int n_in,
                              void* d_out, int out_size)
{
    const float* tgt   = (const float*)d_in[0];
    const float* mem   = (const float*)d_in[1];
    const float* sh    = (const float*)d_in[2];
    const float* dist  = (const float*)d_in[3];
    const float* Wq    = (const float*)d_in[4];
    const float* Wk    = (const float*)d_in[5];
    const float* Wv    = (const float*)d_in[6];
    const float* Wo    = (const float*)d_in[7];
    const float* gw1   = (const float*)d_in[8];
    const float* gb1   = (const float*)d_in[9];
    const float* gw2   = (const float*)d_in[10];
    const float* gb2   = (const float*)d_in[11];
    const float* ln1g  = (const float*)d_in[12];
    const float* ln1b  = (const float*)d_in[13];
    const float* ln2g  = (const float*)d_in[14];
    const float* ln2b  = (const float*)d_in[15];
    const float* ffw1  = (const float*)d_in[16];
    const float* ffd1  = (const float*)d_in[17];
    const float* ffw2  = (const float*)d_in[18];
    const int*   idxp  = (const int*)d_in[19];
    float* out = (float*)d_out;

    float *q, *k, *v, *t2, *t2o, *y, *h1, *ff;
    cudaGetSymbolAddress((void**)&q,   g_q);
    cudaGetSymbolAddress((void**)&k,   g_k);
    cudaGetSymbolAddress((void**)&v,   g_v);
    cudaGetSymbolAddress((void**)&t2,  g_t2);
    cudaGetSymbolAddress((void**)&t2o, g_t2o);
    cudaGetSymbolAddress((void**)&y,   g_y);
    cudaGetSymbolAddress((void**)&h1,  g_h1);
    cudaGetSymbolAddress((void**)&ff,  g_ff);

    const int NT = PP / 32;   // 625 point tiles

    vn_gemm2<DD><<<NT, 128>>>(tgt, Wq, q);
    vn_gemm2<DD><<<NT, 128>>>(mem, Wk, k);
    vn_gemm2<DD><<<NT, 128>>>(mem, Wv, v);

    attn_kernel<<<PP, 128>>>(sh, dist, gw1, gb1, gw2, gb2, idxp);

    vn_gemm2<DD><<<NT, 128>>>(t2, Wo, t2o);
    vn_ln_kernel<<<PP, 128>>>(tgt, t2o, ln1g, ln1b, y);

    vn_ff1_kernel<<<dim3(DFF / 64, NT), 128>>>(y, ffw1, ffd1, h1);
    vn_gemm2<DFF><<<NT, 128>>>(h1, ffw2, ff);
    vn_ln_kernel<<<PP, 128>>>(y, ff, ln2g, ln2b, out);
}